// round 15
// baseline (speedup 1.0000x reference)
#include <cuda_runtime.h>
#include <cuda_fp16.h>
#include <cstdint>

// Problem constants
#define VOCAB  32000
#define EMBED  100
#define HID    128
#define BATCH  1024
#define SEQ    256

// -------- device scratch (no allocation allowed) --------
__device__ __align__(16) float g_P[VOCAB * HID];        // fused projections (16.4 MB)
__device__ __align__(16) __half g_Ehi[VOCAB * 128];     // emb split (padded K=128)
__device__ __align__(16) __half g_Elo[VOCAB * 128];
__device__ __align__(16) __half g_Whi[VOCAB * 128];     // W_fc hi (head is single-term)
__device__ __align__(16) __half g_IHhi[128 * 128];      // W_ih split
__device__ __align__(16) __half g_IHlo[128 * 128];
__device__ __align__(16) __half g_WHhi[128 * 128];      // W_hh split
__device__ __align__(16) __half g_WHlo[128 * 128];
__device__ __align__(16) __half g_Hhi[BATCH * 128];     // h_last (fp16)

// ============================================================================
// Pre-split conversion: fp32 [rows][Kv] -> hi/lo fp16 [rows][128] (zero-pad).
// ============================================================================
__global__ void __launch_bounds__(256) k_cvt(
    const float* __restrict__ src, int Kv,
    __half* __restrict__ hi, __half* __restrict__ lo)
{
    const int r    = blockIdx.x * 8 + (threadIdx.x >> 5);
    const int lane = threadIdx.x & 31;
    #pragma unroll
    for (int cp = lane; cp < 64; cp += 32) {
        const int c0 = 2 * cp;
        float a = (c0     < Kv) ? src[(long long)r * Kv + c0]     : 0.0f;
        float b = (c0 + 1 < Kv) ? src[(long long)r * Kv + c0 + 1] : 0.0f;
        __half ha = __float2half_rn(a), hb = __float2half_rn(b);
        __half la = __float2half_rn(a - __half2float(ha));
        __half lb = __float2half_rn(b - __half2float(hb));
        ((uint32_t*)hi)[r * 64 + cp] = (uint32_t)*(uint16_t*)&ha | ((uint32_t)*(uint16_t*)&hb << 16);
        ((uint32_t*)lo)[r * 64 + cp] = (uint32_t)*(uint16_t*)&la | ((uint32_t)*(uint16_t*)&lb << 16);
    }
}
// hi-only variant (head never reads W_fc lo)
__global__ void __launch_bounds__(256) k_cvt_hi(
    const float* __restrict__ src, int Kv, __half* __restrict__ hi)
{
    const int r    = blockIdx.x * 8 + (threadIdx.x >> 5);
    const int lane = threadIdx.x & 31;
    #pragma unroll
    for (int cp = lane; cp < 64; cp += 32) {
        const int c0 = 2 * cp;
        float a = (c0     < Kv) ? src[(long long)r * Kv + c0]     : 0.0f;
        float b = (c0 + 1 < Kv) ? src[(long long)r * Kv + c0 + 1] : 0.0f;
        __half ha = __float2half_rn(a), hb = __float2half_rn(b);
        ((uint32_t*)hi)[r * 64 + cp] = (uint32_t)*(uint16_t*)&ha | ((uint32_t)*(uint16_t*)&hb << 16);
    }
}

// ============================================================================
// mma.sync helpers (fp16 in / fp32 accum)
// ============================================================================
__device__ __forceinline__ uint32_t smem_u32(const void* p) {
    uint32_t a;
    asm("{ .reg .u64 t; cvta.to.shared.u64 t, %1; cvt.u32.u64 %0, t; }" : "=r"(a) : "l"(p));
    return a;
}
__device__ __forceinline__ void ldmx4(uint32_t* r, uint32_t a) {
    asm volatile("ldmatrix.sync.aligned.m8n8.x4.shared.b16 {%0,%1,%2,%3}, [%4];"
                 : "=r"(r[0]), "=r"(r[1]), "=r"(r[2]), "=r"(r[3]) : "r"(a));
}
__device__ __forceinline__ void ldmx2(uint32_t* r, uint32_t a) {
    asm volatile("ldmatrix.sync.aligned.m8n8.x2.shared.b16 {%0,%1}, [%2];"
                 : "=r"(r[0]), "=r"(r[1]) : "r"(a));
}
__device__ __forceinline__ void mma_f16(float* c, const uint32_t* a,
                                        uint32_t b0, uint32_t b1) {
    asm volatile("mma.sync.aligned.m16n8k16.row.col.f32.f16.f16.f32 "
                 "{%0,%1,%2,%3}, {%4,%5,%6,%7}, {%8,%9}, {%0,%1,%2,%3};"
                 : "+f"(c[0]), "+f"(c[1]), "+f"(c[2]), "+f"(c[3])
                 : "r"(a[0]), "r"(a[1]), "r"(a[2]), "r"(a[3]), "r"(b0), "r"(b1));
}
__device__ __forceinline__ uint32_t tswz(int row, int u) {
    return (uint32_t)(row * 256 + ((u ^ (row & 7)) << 4));
}
__device__ __forceinline__ void load_tile(const __half* __restrict__ g,
                                          char* s, int rows, int tid) {
    #pragma unroll 4
    for (int i = tid; i < rows * 16; i += 256) {
        int row = i >> 4, u = i & 15;
        *(uint4*)(s + tswz(row, u)) = *(const uint4*)(g + (long long)row * 128 + u * 8);
    }
}
__device__ __forceinline__ float fast_tanh(float x) {
    float e = __expf(2.0f * x);
    return 1.0f - __fdividef(2.0f, e + 1.0f);
}
__device__ __forceinline__ uint32_t pack_h2(float a, float b) {
    __half ha = __float2half_rn(a), hb = __float2half_rn(b);
    return (uint32_t)*(uint16_t*)&ha | ((uint32_t)*(uint16_t*)&hb << 16);
}
__device__ __forceinline__ uint32_t mapa_peer(uint32_t addr, uint32_t rank) {
    uint32_t r;
    asm("mapa.shared::cluster.u32 %0, %1, %2;" : "=r"(r) : "r"(addr), "r"(rank));
    return r;
}
__device__ __forceinline__ uint32_t my_cluster_rank() {
    uint32_t r;
    asm("mov.u32 %0, %%cluster_ctarank;" : "=r"(r));
    return r;
}
#define CLUSTER_SYNC() do { \
    asm volatile("barrier.cluster.arrive.aligned;" ::: "memory"); \
    asm volatile("barrier.cluster.wait.aligned;" ::: "memory"); } while (0)
#define MBAR_INIT(a, c) \
    asm volatile("mbarrier.init.shared.b64 [%0], %1;" :: "r"(a), "r"(c) : "memory")
#define MBAR_EXPECT_TX(a, bytes) \
    asm volatile("mbarrier.arrive.expect_tx.shared.b64 _, [%0], %1;" :: "r"(a), "r"(bytes) : "memory")
#define ST_ASYNC_U32(raddr, val, rmbar) \
    asm volatile("st.async.weak.shared::cluster.mbarrier::complete_tx::bytes.b32 [%0], %1, [%2];" \
                 :: "r"(raddr), "r"(val), "r"(rmbar) : "memory")
__device__ __forceinline__ void mbar_wait_acq(uint32_t mbar, uint32_t parity) {
    uint32_t done;
    asm volatile("{\n\t.reg .pred p;\n\t"
                 "mbarrier.try_wait.parity.acquire.cluster.shared::cta.b64 p, [%1], %2;\n\t"
                 "selp.b32 %0, 1, 0, p;\n\t}" : "=r"(done) : "r"(mbar), "r"(parity) : "memory");
    if (!done) {
        asm volatile("{\n\t.reg .pred P1;\n\tWL%=:\n\t"
                     "mbarrier.try_wait.parity.acquire.cluster.shared::cta.b64 P1, [%0], %1;\n\t"
                     "@P1 bra.uni WD%=;\n\tbra.uni WL%=;\n\tWD%=:\n\t}"
                     :: "r"(mbar), "r"(parity) : "memory");
    }
}
#define CP_ASYNC16(dst, src) \
    asm volatile("cp.async.cg.shared.global [%0], [%1], 16;" :: "r"(dst), "l"(src) : "memory")
#define CP_COMMIT() asm volatile("cp.async.commit_group;" ::: "memory")
#define CP_WAIT0()  asm volatile("cp.async.wait_group 0;" ::: "memory")

// ============================================================================
// k_gemm: 3-term split GEMM (P projection). Unchanged from passing R11-14.
// ============================================================================
#define A_TILE 32768
#define B_TILE 16384
#define GEMM_SMEM (2 * A_TILE + 2 * B_TILE)   // 98304
#define EPAD 68

__global__ void __launch_bounds__(256, 2) k_gemm(
    const __half* __restrict__ Ahi_g, const __half* __restrict__ Alo_g,
    const __half* __restrict__ Bhi_g, const __half* __restrict__ Blo_g,
    float* __restrict__ out, long long ldout,
    const float* __restrict__ bias1, const float* __restrict__ bias2)
{
    extern __shared__ __align__(16) char sm[];
    __shared__ float sbias[64];
    char* Ahi = sm;
    char* Alo = sm + A_TILE;
    char* Bhi = sm + 2 * A_TILE;
    char* Blo = sm + 2 * A_TILE + B_TILE;

    const int tid = threadIdx.x, w = tid >> 5, lane = tid & 31;
    const int wm = w >> 1, wn = w & 1;
    const int m0 = blockIdx.x * 128, n0 = blockIdx.y * 64;

    load_tile(Ahi_g + (long long)m0 * 128, Ahi, 128, tid);
    load_tile(Alo_g + (long long)m0 * 128, Alo, 128, tid);
    load_tile(Bhi_g + (long long)n0 * 128, Bhi, 64, tid);
    load_tile(Blo_g + (long long)n0 * 128, Blo, 64, tid);
    if (tid < 64) sbias[tid] = bias1[n0 + tid] + (bias2 ? bias2[n0 + tid] : 0.0f);
    __syncthreads();

    const int sw = lane & 7;
    const int arow = wm * 32 + (lane & 15);
    const int akh  = lane >> 4;
    const int brow = wn * 32 + (lane & 7) + 8 * (lane >> 4);
    const int bkh  = (lane >> 3) & 1;

    const uint32_t sA0h = smem_u32(Ahi) + arow * 256;
    const uint32_t sA0l = smem_u32(Alo) + arow * 256;
    const uint32_t sB0h = smem_u32(Bhi) + brow * 256;
    const uint32_t sB0l = smem_u32(Blo) + brow * 256;

    float acc[2][4][4];
    #pragma unroll
    for (int mt = 0; mt < 2; mt++)
        #pragma unroll
        for (int nt = 0; nt < 4; nt++)
            #pragma unroll
            for (int q = 0; q < 4; q++) acc[mt][nt][q] = 0.0f;

    #pragma unroll
    for (int ks = 0; ks < 8; ks++) {
        const uint32_t uA = (uint32_t)(((2 * ks + akh) ^ sw) << 4);
        const uint32_t uB = (uint32_t)(((2 * ks + bkh) ^ sw) << 4);
        uint32_t aHi[2][4], aLo[2][4];
        ldmx4(aHi[0], sA0h + uA);
        ldmx4(aHi[1], sA0h + 16 * 256 + uA);
        ldmx4(aLo[0], sA0l + uA);
        ldmx4(aLo[1], sA0l + 16 * 256 + uA);
        #pragma unroll
        for (int np = 0; np < 2; np++) {
            uint32_t bh[4], bl[4];
            ldmx4(bh, sB0h + np * 16 * 256 + uB);
            ldmx4(bl, sB0l + np * 16 * 256 + uB);
            #pragma unroll
            for (int mt = 0; mt < 2; mt++) {
                mma_f16(acc[mt][2 * np],     aHi[mt], bh[0], bh[1]);
                mma_f16(acc[mt][2 * np + 1], aHi[mt], bh[2], bh[3]);
                mma_f16(acc[mt][2 * np],     aLo[mt], bh[0], bh[1]);
                mma_f16(acc[mt][2 * np + 1], aLo[mt], bh[2], bh[3]);
                mma_f16(acc[mt][2 * np],     aHi[mt], bl[0], bl[1]);
                mma_f16(acc[mt][2 * np + 1], aHi[mt], bl[2], bl[3]);
            }
        }
    }

    __syncthreads();
    float* stg = (float*)sm;
    const int g = lane >> 2, tig = lane & 3;
    #pragma unroll
    for (int mt = 0; mt < 2; mt++) {
        const int r0 = wm * 32 + mt * 16 + g;
        #pragma unroll
        for (int nt = 0; nt < 4; nt++) {
            const int col = wn * 32 + nt * 8 + 2 * tig;
            *(float2*)(stg + r0 * EPAD + col)       = make_float2(acc[mt][nt][0], acc[mt][nt][1]);
            *(float2*)(stg + (r0 + 8) * EPAD + col) = make_float2(acc[mt][nt][2], acc[mt][nt][3]);
        }
    }
    __syncthreads();
    #pragma unroll 4
    for (int i = tid; i < 128 * 16; i += 256) {
        const int row = i >> 4, u = i & 15, col = u * 4;
        float4 v = *(const float4*)(stg + row * EPAD + col);
        v.x += sbias[col]; v.y += sbias[col + 1]; v.z += sbias[col + 2]; v.w += sbias[col + 3];
        *(float4*)(out + (long long)(m0 + row) * ldout + n0 + col) = v;
    }
}

// ============================================================================
// k_head: persistent-strip single-term fp16 head GEMM (unchanged from R12-14).
// ============================================================================
#define NT_STRIP 10
#define HD_SMEM (A_TILE + 2 * B_TILE + NT_STRIP * 64 * 4)

__global__ void __launch_bounds__(256, 2) k_head(
    const __half* __restrict__ Ahi_g, const __half* __restrict__ Bhi_g,
    float* __restrict__ out, const float* __restrict__ bias)
{
    extern __shared__ __align__(16) char sm[];
    char* A  = sm;
    char* Bb = sm + A_TILE;
    float* sbias = (float*)(sm + A_TILE + 2 * B_TILE);

    const int tid = threadIdx.x, w = tid >> 5, lane = tid & 31;
    const int wm = w >> 1, wn = w & 1;
    const int m0 = blockIdx.x * 128;
    const int nbase = blockIdx.y * (NT_STRIP * 64);

    {
        const __half* Ag = Ahi_g + (long long)m0 * 128;
        #pragma unroll 2
        for (int i = tid; i < 128 * 16; i += 256) {
            int row = i >> 4, u = i & 15;
            CP_ASYNC16(smem_u32(A + tswz(row, u)), Ag + (long long)row * 128 + u * 8);
        }
        const __half* Bg = Bhi_g + (long long)nbase * 128;
        for (int i = tid; i < 64 * 16; i += 256) {
            int row = i >> 4, u = i & 15;
            CP_ASYNC16(smem_u32(Bb + tswz(row, u)), Bg + (long long)row * 128 + u * 8);
        }
        CP_COMMIT();
        for (int i = tid; i < NT_STRIP * 64; i += 256) sbias[i] = bias[nbase + i];
        CP_WAIT0();
        __syncthreads();
    }

    const int sw = lane & 7;
    const int arow = wm * 32 + (lane & 15);
    const int akh  = lane >> 4;
    const int brow = wn * 32 + (lane & 7) + 8 * (lane >> 4);
    const int bkh  = (lane >> 3) & 1;
    const uint32_t sA0 = smem_u32(A) + arow * 256;
    const int g = lane >> 2, tig = lane & 3;

    int buf = 0;
    for (int ti = 0; ti < NT_STRIP; ti++) {
        if (ti < NT_STRIP - 1) {
            const __half* Bg = Bhi_g + (long long)(nbase + (ti + 1) * 64) * 128;
            char* Bn = Bb + (buf ^ 1) * B_TILE;
            for (int i = tid; i < 64 * 16; i += 256) {
                int row = i >> 4, u = i & 15;
                CP_ASYNC16(smem_u32(Bn + tswz(row, u)), Bg + (long long)row * 128 + u * 8);
            }
            CP_COMMIT();
        }

        const uint32_t sB0 = smem_u32(Bb + buf * B_TILE) + brow * 256;
        float acc[2][4][4];
        #pragma unroll
        for (int mt = 0; mt < 2; mt++)
            #pragma unroll
            for (int nt = 0; nt < 4; nt++)
                #pragma unroll
                for (int q = 0; q < 4; q++) acc[mt][nt][q] = 0.0f;

        #pragma unroll
        for (int ks = 0; ks < 8; ks++) {
            const uint32_t uA = (uint32_t)(((2 * ks + akh) ^ sw) << 4);
            const uint32_t uB = (uint32_t)(((2 * ks + bkh) ^ sw) << 4);
            uint32_t aHi[2][4];
            ldmx4(aHi[0], sA0 + uA);
            ldmx4(aHi[1], sA0 + 16 * 256 + uA);
            #pragma unroll
            for (int np = 0; np < 2; np++) {
                uint32_t bh[4];
                ldmx4(bh, sB0 + np * 16 * 256 + uB);
                #pragma unroll
                for (int mt = 0; mt < 2; mt++) {
                    mma_f16(acc[mt][2 * np],     aHi[mt], bh[0], bh[1]);
                    mma_f16(acc[mt][2 * np + 1], aHi[mt], bh[2], bh[3]);
                }
            }
        }

        const int n0 = nbase + ti * 64;
        #pragma unroll
        for (int mt = 0; mt < 2; mt++) {
            const long long r0 = (long long)(m0 + wm * 32 + mt * 16 + g) * VOCAB + n0;
            const long long r1 = r0 + 8LL * VOCAB;
            #pragma unroll
            for (int nt = 0; nt < 4; nt++) {
                const int col = wn * 32 + nt * 8 + 2 * tig;
                const float bx = sbias[ti * 64 + col], by = sbias[ti * 64 + col + 1];
                *(float2*)(out + r0 + col) = make_float2(acc[mt][nt][0] + bx, acc[mt][nt][1] + by);
                *(float2*)(out + r1 + col) = make_float2(acc[mt][nt][2] + bx, acc[mt][nt][3] + by);
            }
        }

        if (ti < NT_STRIP - 1) {
            CP_WAIT0();
            __syncthreads();
            buf ^= 1;
        }
    }
}

// ============================================================================
// Kernel B: cluster-of-2 MMA RNN scan, 2-term, LATENCY-PIPELINED:
// per step, MMA over the LOCAL k-half (cols this CTA computed — visible right
// after __syncthreads) runs FIRST, covering the peer half's DSMEM flight
// (~215cy) + mbar wakeup; then wait; then the REMOTE k-half. mbar0 is
// pre-credited in the prologue with the h0=0 exchange so parity stays
// (t>>1)&1. One __syncthreads per step still guards the double buffer.
// ============================================================================
#define SXP 260
#define S2_OFF_W    0                         // local 64 W rows: hi 16KB + lo 16KB
#define S2_OFF_AT   32768                     // A tiles: buf*4096, hi only (8KB)
#define S2_OFF_SX   40960                     // 16 x SXP ints (16640 B)
#define S2_OFF_MBAR (S2_OFF_SX + 16 * SXP * 4)
#define S2_SMEM     (S2_OFF_MBAR + 64)

__global__ void __launch_bounds__(256, 1) __cluster_dims__(2, 1, 1)
k_rnn_cluster(const int* __restrict__ x)
{
    extern __shared__ __align__(16) char sm[];
    char* WHhi = sm + S2_OFF_W;
    char* WHlo = sm + S2_OFF_W + 16384;
    char* AT   = sm + S2_OFF_AT;
    int*  sx   = (int*)(sm + S2_OFF_SX);

    const int tid = threadIdx.x, w = tid >> 5, lane = tid & 31;
    const uint32_t rank = my_cluster_rank();
    const uint32_t peer = rank ^ 1;
    const int b0 = (blockIdx.x >> 1) * 16;
    const uint32_t mbar0 = smem_u32(sm) + S2_OFF_MBAR;
    const uint32_t mbar1 = mbar0 + 8;

    // prologue: local W half, x stage, zero h buffer 0, mbar init
    load_tile(g_WHhi + (long long)rank * 64 * 128, WHhi, 64, tid);
    load_tile(g_WHlo + (long long)rank * 64 * 128, WHlo, 64, tid);
    for (int i = tid; i < 16 * SEQ; i += 256) {
        int row = i >> 8, t = i & 255;
        sx[row * SXP + t] = x[(b0 + row) * SEQ + t];
    }
    for (int i = tid; i < 512; i += 256)
        ((uint4*)AT)[i] = make_uint4(0, 0, 0, 0);
    if (tid == 0) { MBAR_INIT(mbar0, 1); MBAR_INIT(mbar1, 1); }
    __syncthreads();

    // preload B fragments (W_hh local rows w*8..w*8+8, full K) — static
    const int l15 = lane & 15;
    const int browB = w * 8 + (l15 & 7);
    const int bkhB  = (l15 >> 3) & 1;
    const int swB   = l15 & 7;
    const uint32_t sBh = smem_u32(WHhi) + browB * 256;
    const uint32_t sBl = smem_u32(WHlo) + browB * 256;
    uint32_t bfh[8][2], bfl[8][2];
    #pragma unroll
    for (int ks = 0; ks < 8; ks++) {
        const uint32_t uB = (uint32_t)(((2 * ks + bkhB) ^ swB) << 4);
        ldmx2(bfh[ks], sBh + uB);
        ldmx2(bfl[ks], sBl + uB);
    }

    // A-frag addressing
    const int arow = lane & 15;
    const int akh  = lane >> 4;
    const int swA  = lane & 7;
    const uint32_t sAT = smem_u32(AT);
    const uint32_t aH0 = sAT + arow * 256;

    // local/remote k-split: local ks cover THIS CTA's output cols
    const int ksL0 = (int)rank * 4;
    const int ksR0 = (int)peer * 4;

    // epilogue addressing: thread owns rows g, g+8; cols jc = rank*64+w*8+2*tig
    const int g = lane >> 2, tig = lane & 3;
    const int jc = (int)rank * 64 + w * 8 + 2 * tig;
    const int ustore = (int)rank * 8 + w;
    const uint32_t st0 = (uint32_t)(g * 256 + ((ustore ^ (g & 7)) << 4) + 4 * tig);
    const uint32_t st1 = (uint32_t)((g + 8) * 256 + ((ustore ^ ((g + 8) & 7)) << 4) + 4 * tig);

    // mbar init on both CTAs must complete before any remote traffic
    CLUSTER_SYNC();
    const uint32_t peerAT    = mapa_peer(sAT, peer);
    const uint32_t peerMbar0 = mapa_peer(mbar0, peer);
    const uint32_t peerMbar1 = mapa_peer(mbar1, peer);

    // pre-credit mbar0 with the h0=0 exchange (buf0 peer halves are zero
    // anyway; this just completes mbar0 phase 0 so t=0's wait passes)
    if (tid == 0) MBAR_EXPECT_TX(mbar0, 2048);
    __syncthreads();
    ST_ASYNC_U32(peerAT + st0, 0u, peerMbar0);
    ST_ASYNC_U32(peerAT + st1, 0u, peerMbar0);

    int cur = 0;
    for (int t = 0; t < SEQ; t++) {
        const uint32_t myMbar = (t & 1) ? mbar1 : mbar0;        // h(t) remote arrivals
        const uint32_t nMbarP = (t & 1) ? peerMbar0 : peerMbar1; // credit for h(t+1)
        const uint32_t nMbarL = (t & 1) ? mbar0 : mbar1;
        if (tid == 0) MBAR_EXPECT_TX(nMbarL, 2048);   // before any h(t+1) st.async

        // P gather (consumed at epilogue; L2 latency hides under MMA)
        const int idx0 = sx[g * SXP + t];
        const int idx1 = sx[(g + 8) * SXP + t];
        const float2 p0 = *(const float2*)(g_P + idx0 * HID + jc);
        const float2 p1 = *(const float2*)(g_P + idx1 * HID + jc);

        float aH[4] = {0, 0, 0, 0}, aM[4] = {0, 0, 0, 0};
        const uint32_t aAddrH = aH0 + cur * 4096;

        // phase 1: LOCAL k-half (visible since last __syncthreads) — covers
        // the peer half's DSMEM flight
        #pragma unroll
        for (int i = 0; i < 4; i++) {
            const int ks = ksL0 + i;
            const uint32_t uA = (uint32_t)(((2 * ks + akh) ^ swA) << 4);
            uint32_t ahi[4];
            ldmx4(ahi, aAddrH + uA);
            mma_f16(aH, ahi, bfh[ks][0], bfh[ks][1]);
            mma_f16(aM, ahi, bfl[ks][0], bfl[ks][1]);
        }

        // phase 2: wait for remote h(t) half (should hit the fast path)
        mbar_wait_acq(myMbar, (uint32_t)((t >> 1) & 1));

        // phase 3: REMOTE k-half
        #pragma unroll
        for (int i = 0; i < 4; i++) {
            const int ks = ksR0 + i;
            const uint32_t uA = (uint32_t)(((2 * ks + akh) ^ swA) << 4);
            uint32_t ahi[4];
            ldmx4(ahi, aAddrH + uA);
            mma_f16(aH, ahi, bfh[ks][0], bfh[ks][1]);
            mma_f16(aM, ahi, bfl[ks][0], bfl[ks][1]);
        }

        // epilogue: h(t+1) = tanh(mma + P); store local + st.async to peer
        const int nxt = cur ^ 1;
        char* DhiL = AT + nxt * 4096;
        const uint32_t DhiR = peerAT + nxt * 4096;
        const float h00 = fast_tanh(aH[0] + aM[0] + p0.x);
        const float h01 = fast_tanh(aH[1] + aM[1] + p0.y);
        const float h10 = fast_tanh(aH[2] + aM[2] + p1.x);
        const float h11 = fast_tanh(aH[3] + aM[3] + p1.y);
        const uint32_t hi0 = pack_h2(h00, h01);
        const uint32_t hi1 = pack_h2(h10, h11);
        *(uint32_t*)(DhiL + st0) = hi0;
        *(uint32_t*)(DhiL + st1) = hi1;
        ST_ASYNC_U32(DhiR + st0, hi0, nMbarP);
        ST_ASYNC_U32(DhiR + st1, hi1, nMbarP);

        __syncthreads();          // local h(t+1) half visible for next local MMA
        cur = nxt;
    }

    // write final h — rank 0 only (local halves of final buffer are complete;
    // remote half arrived via st.async of last step? rank0 needs cols 64-127:
    // they were st.async'd crediting mbar[(255+1)&1] = mbar0 — wait for them)
    mbar_wait_acq((SEQ & 1) ? mbar1 : mbar0, (uint32_t)((SEQ >> 1) & 1));
    if (rank == 0) {
        char* Fhi = AT + cur * 4096;
        for (int i = tid; i < 16 * 64; i += 256) {
            const int row = i >> 6, cp = i & 63;
            const uint32_t off = (uint32_t)(row * 256 + (((cp >> 2) ^ (row & 7)) << 4) + (cp & 3) * 4);
            ((uint32_t*)g_Hhi)[(b0 + row) * 64 + cp] = *(const uint32_t*)(Fhi + off);
        }
    }
    CLUSTER_SYNC();   // no CTA exits while peer traffic may be in flight
}

// ============================================================================
// launch
// ============================================================================
extern "C" void kernel_launch(void* const* d_in, const int* in_sizes, int n_in,
                              void* d_out, int out_size) {
    const int*   x    = (const int*)d_in[0];     // int32: JAX downcasts int64
    const float* emb  = (const float*)d_in[1];
    const float* W_ih = (const float*)d_in[2];
    const float* W_hh = (const float*)d_in[3];
    const float* b_ih = (const float*)d_in[4];
    const float* b_hh = (const float*)d_in[5];
    const float* W_fc = (const float*)d_in[6];
    const float* b_fc = (const float*)d_in[7];
    float*       out  = (float*)d_out;

    static float* P_p = nullptr;
    static __half *Ehi_p, *Elo_p, *Whi_p, *IHhi_p, *IHlo_p;
    static __half *WHhi_p, *WHlo_p, *Hhi_p;
    if (!P_p) {
        cudaGetSymbolAddress((void**)&P_p,    g_P);
        cudaGetSymbolAddress((void**)&Ehi_p,  g_Ehi);
        cudaGetSymbolAddress((void**)&Elo_p,  g_Elo);
        cudaGetSymbolAddress((void**)&Whi_p,  g_Whi);
        cudaGetSymbolAddress((void**)&IHhi_p, g_IHhi);
        cudaGetSymbolAddress((void**)&IHlo_p, g_IHlo);
        cudaGetSymbolAddress((void**)&WHhi_p, g_WHhi);
        cudaGetSymbolAddress((void**)&WHlo_p, g_WHlo);
        cudaGetSymbolAddress((void**)&Hhi_p,  g_Hhi);
        cudaFuncSetAttribute(k_gemm,        cudaFuncAttributeMaxDynamicSharedMemorySize, GEMM_SMEM);
        cudaFuncSetAttribute(k_head,        cudaFuncAttributeMaxDynamicSharedMemorySize, HD_SMEM);
        cudaFuncSetAttribute(k_rnn_cluster, cudaFuncAttributeMaxDynamicSharedMemorySize, S2_SMEM);
    }

    // pre-split to hi/lo fp16 (K padded to 128); W_fc needs hi only
    k_cvt<<<VOCAB / 8, 256>>>(emb,  EMBED, Ehi_p,  Elo_p);
    k_cvt<<<HID / 8,   256>>>(W_ih, EMBED, IHhi_p, IHlo_p);
    k_cvt<<<HID / 8,   256>>>(W_hh, HID,   WHhi_p, WHlo_p);
    k_cvt_hi<<<VOCAB / 8, 256>>>(W_fc, HID, Whi_p);

    // P[v][j] = emb[v]·W_ih[j] + (b_ih+b_hh)[j]  (3-term: P near-fp32)
    k_gemm<<<dim3(VOCAB / 128, HID / 64), 256, GEMM_SMEM>>>(
        Ehi_p, Elo_p, IHhi_p, IHlo_p, P_p, HID, b_ih, b_hh);

    // recurrent scan: cluster-of-2, 2-term, local/remote latency-pipelined
    k_rnn_cluster<<<BATCH / 8, 256, S2_SMEM>>>(x);

    // head: persistent-strip single-term fp16
    k_head<<<dim3(BATCH / 128, VOCAB / (NT_STRIP * 64)), 256, HD_SMEM>>>(
        Hhi_p, Whi_p, out, b_fc);
}

// round 16
// speedup vs baseline: 1.0914x; 1.0914x over previous
#include <cuda_runtime.h>
#include <cuda_fp16.h>
#include <cstdint>

// Problem constants
#define VOCAB  32000
#define EMBED  100
#define HID    128
#define BATCH  1024
#define SEQ    256

// -------- device scratch (no allocation allowed) --------
__device__ __align__(16) float g_P[VOCAB * HID];        // fused projections (16.4 MB)
__device__ __align__(16) __half g_Ehi[VOCAB * 128];     // emb split (padded K=128)
__device__ __align__(16) __half g_Elo[VOCAB * 128];
__device__ __align__(16) __half g_Whi[VOCAB * 128];     // W_fc hi (head is single-term)
__device__ __align__(16) __half g_IHhi[128 * 128];      // W_ih split
__device__ __align__(16) __half g_IHlo[128 * 128];
__device__ __align__(16) __half g_WHhi[128 * 128];      // W_hh split
__device__ __align__(16) __half g_WHlo[128 * 128];
__device__ __align__(16) __half g_Hhi[BATCH * 128];     // h_last (fp16)

// ============================================================================
// Pre-split conversion: fp32 [rows][Kv] -> hi/lo fp16 [rows][128] (zero-pad).
// ============================================================================
__global__ void __launch_bounds__(256) k_cvt(
    const float* __restrict__ src, int Kv,
    __half* __restrict__ hi, __half* __restrict__ lo)
{
    const int r    = blockIdx.x * 8 + (threadIdx.x >> 5);
    const int lane = threadIdx.x & 31;
    #pragma unroll
    for (int cp = lane; cp < 64; cp += 32) {
        const int c0 = 2 * cp;
        float a = (c0     < Kv) ? src[(long long)r * Kv + c0]     : 0.0f;
        float b = (c0 + 1 < Kv) ? src[(long long)r * Kv + c0 + 1] : 0.0f;
        __half ha = __float2half_rn(a), hb = __float2half_rn(b);
        __half la = __float2half_rn(a - __half2float(ha));
        __half lb = __float2half_rn(b - __half2float(hb));
        ((uint32_t*)hi)[r * 64 + cp] = (uint32_t)*(uint16_t*)&ha | ((uint32_t)*(uint16_t*)&hb << 16);
        ((uint32_t*)lo)[r * 64 + cp] = (uint32_t)*(uint16_t*)&la | ((uint32_t)*(uint16_t*)&lb << 16);
    }
}
// hi-only variant (head never reads W_fc lo)
__global__ void __launch_bounds__(256) k_cvt_hi(
    const float* __restrict__ src, int Kv, __half* __restrict__ hi)
{
    const int r    = blockIdx.x * 8 + (threadIdx.x >> 5);
    const int lane = threadIdx.x & 31;
    #pragma unroll
    for (int cp = lane; cp < 64; cp += 32) {
        const int c0 = 2 * cp;
        float a = (c0     < Kv) ? src[(long long)r * Kv + c0]     : 0.0f;
        float b = (c0 + 1 < Kv) ? src[(long long)r * Kv + c0 + 1] : 0.0f;
        __half ha = __float2half_rn(a), hb = __float2half_rn(b);
        ((uint32_t*)hi)[r * 64 + cp] = (uint32_t)*(uint16_t*)&ha | ((uint32_t)*(uint16_t*)&hb << 16);
    }
}

// ============================================================================
// mma.sync helpers (fp16 in / fp32 accum)
// ============================================================================
__device__ __forceinline__ uint32_t smem_u32(const void* p) {
    uint32_t a;
    asm("{ .reg .u64 t; cvta.to.shared.u64 t, %1; cvt.u32.u64 %0, t; }" : "=r"(a) : "l"(p));
    return a;
}
__device__ __forceinline__ void ldmx4(uint32_t* r, uint32_t a) {
    asm volatile("ldmatrix.sync.aligned.m8n8.x4.shared.b16 {%0,%1,%2,%3}, [%4];"
                 : "=r"(r[0]), "=r"(r[1]), "=r"(r[2]), "=r"(r[3]) : "r"(a));
}
__device__ __forceinline__ void ldmx2(uint32_t* r, uint32_t a) {
    asm volatile("ldmatrix.sync.aligned.m8n8.x2.shared.b16 {%0,%1}, [%2];"
                 : "=r"(r[0]), "=r"(r[1]) : "r"(a));
}
__device__ __forceinline__ void mma_f16(float* c, const uint32_t* a,
                                        uint32_t b0, uint32_t b1) {
    asm volatile("mma.sync.aligned.m16n8k16.row.col.f32.f16.f16.f32 "
                 "{%0,%1,%2,%3}, {%4,%5,%6,%7}, {%8,%9}, {%0,%1,%2,%3};"
                 : "+f"(c[0]), "+f"(c[1]), "+f"(c[2]), "+f"(c[3])
                 : "r"(a[0]), "r"(a[1]), "r"(a[2]), "r"(a[3]), "r"(b0), "r"(b1));
}
__device__ __forceinline__ uint32_t tswz(int row, int u) {
    return (uint32_t)(row * 256 + ((u ^ (row & 7)) << 4));
}
__device__ __forceinline__ void load_tile(const __half* __restrict__ g,
                                          char* s, int rows, int tid) {
    #pragma unroll 4
    for (int i = tid; i < rows * 16; i += 256) {
        int row = i >> 4, u = i & 15;
        *(uint4*)(s + tswz(row, u)) = *(const uint4*)(g + (long long)row * 128 + u * 8);
    }
}
__device__ __forceinline__ float fast_tanh(float x) {
    float e = __expf(2.0f * x);
    return 1.0f - __fdividef(2.0f, e + 1.0f);
}
__device__ __forceinline__ uint32_t pack_h2(float a, float b) {
    __half ha = __float2half_rn(a), hb = __float2half_rn(b);
    return (uint32_t)*(uint16_t*)&ha | ((uint32_t)*(uint16_t*)&hb << 16);
}
__device__ __forceinline__ uint32_t mapa_peer(uint32_t addr, uint32_t rank) {
    uint32_t r;
    asm("mapa.shared::cluster.u32 %0, %1, %2;" : "=r"(r) : "r"(addr), "r"(rank));
    return r;
}
__device__ __forceinline__ uint32_t my_cluster_rank() {
    uint32_t r;
    asm("mov.u32 %0, %%cluster_ctarank;" : "=r"(r));
    return r;
}
#define CLUSTER_SYNC() do { \
    asm volatile("barrier.cluster.arrive.aligned;" ::: "memory"); \
    asm volatile("barrier.cluster.wait.aligned;" ::: "memory"); } while (0)
#define MBAR_INIT(a, c) \
    asm volatile("mbarrier.init.shared.b64 [%0], %1;" :: "r"(a), "r"(c) : "memory")
#define MBAR_EXPECT_TX(a, bytes) \
    asm volatile("mbarrier.arrive.expect_tx.shared.b64 _, [%0], %1;" :: "r"(a), "r"(bytes) : "memory")
#define ST_ASYNC_U32(raddr, val, rmbar) \
    asm volatile("st.async.weak.shared::cluster.mbarrier::complete_tx::bytes.b32 [%0], %1, [%2];" \
                 :: "r"(raddr), "r"(val), "r"(rmbar) : "memory")
__device__ __forceinline__ void mbar_wait_acq(uint32_t mbar, uint32_t parity) {
    uint32_t done;
    asm volatile("{\n\t.reg .pred p;\n\t"
                 "mbarrier.try_wait.parity.acquire.cluster.shared::cta.b64 p, [%1], %2;\n\t"
                 "selp.b32 %0, 1, 0, p;\n\t}" : "=r"(done) : "r"(mbar), "r"(parity) : "memory");
    if (!done) {
        asm volatile("{\n\t.reg .pred P1;\n\tWL%=:\n\t"
                     "mbarrier.try_wait.parity.acquire.cluster.shared::cta.b64 P1, [%0], %1;\n\t"
                     "@P1 bra.uni WD%=;\n\tbra.uni WL%=;\n\tWD%=:\n\t}"
                     :: "r"(mbar), "r"(parity) : "memory");
    }
}
#define CP_ASYNC16(dst, src) \
    asm volatile("cp.async.cg.shared.global [%0], [%1], 16;" :: "r"(dst), "l"(src) : "memory")
#define CP_COMMIT() asm volatile("cp.async.commit_group;" ::: "memory")
#define CP_WAIT0()  asm volatile("cp.async.wait_group 0;" ::: "memory")

// ============================================================================
// k_gemm: 3-term split GEMM (P projection). Unchanged from passing R11-14.
// ============================================================================
#define A_TILE 32768
#define B_TILE 16384
#define GEMM_SMEM (2 * A_TILE + 2 * B_TILE)   // 98304
#define EPAD 68

__global__ void __launch_bounds__(256, 2) k_gemm(
    const __half* __restrict__ Ahi_g, const __half* __restrict__ Alo_g,
    const __half* __restrict__ Bhi_g, const __half* __restrict__ Blo_g,
    float* __restrict__ out, long long ldout,
    const float* __restrict__ bias1, const float* __restrict__ bias2)
{
    extern __shared__ __align__(16) char sm[];
    __shared__ float sbias[64];
    char* Ahi = sm;
    char* Alo = sm + A_TILE;
    char* Bhi = sm + 2 * A_TILE;
    char* Blo = sm + 2 * A_TILE + B_TILE;

    const int tid = threadIdx.x, w = tid >> 5, lane = tid & 31;
    const int wm = w >> 1, wn = w & 1;
    const int m0 = blockIdx.x * 128, n0 = blockIdx.y * 64;

    load_tile(Ahi_g + (long long)m0 * 128, Ahi, 128, tid);
    load_tile(Alo_g + (long long)m0 * 128, Alo, 128, tid);
    load_tile(Bhi_g + (long long)n0 * 128, Bhi, 64, tid);
    load_tile(Blo_g + (long long)n0 * 128, Blo, 64, tid);
    if (tid < 64) sbias[tid] = bias1[n0 + tid] + (bias2 ? bias2[n0 + tid] : 0.0f);
    __syncthreads();

    const int sw = lane & 7;
    const int arow = wm * 32 + (lane & 15);
    const int akh  = lane >> 4;
    const int brow = wn * 32 + (lane & 7) + 8 * (lane >> 4);
    const int bkh  = (lane >> 3) & 1;

    const uint32_t sA0h = smem_u32(Ahi) + arow * 256;
    const uint32_t sA0l = smem_u32(Alo) + arow * 256;
    const uint32_t sB0h = smem_u32(Bhi) + brow * 256;
    const uint32_t sB0l = smem_u32(Blo) + brow * 256;

    float acc[2][4][4];
    #pragma unroll
    for (int mt = 0; mt < 2; mt++)
        #pragma unroll
        for (int nt = 0; nt < 4; nt++)
            #pragma unroll
            for (int q = 0; q < 4; q++) acc[mt][nt][q] = 0.0f;

    #pragma unroll
    for (int ks = 0; ks < 8; ks++) {
        const uint32_t uA = (uint32_t)(((2 * ks + akh) ^ sw) << 4);
        const uint32_t uB = (uint32_t)(((2 * ks + bkh) ^ sw) << 4);
        uint32_t aHi[2][4], aLo[2][4];
        ldmx4(aHi[0], sA0h + uA);
        ldmx4(aHi[1], sA0h + 16 * 256 + uA);
        ldmx4(aLo[0], sA0l + uA);
        ldmx4(aLo[1], sA0l + 16 * 256 + uA);
        #pragma unroll
        for (int np = 0; np < 2; np++) {
            uint32_t bh[4], bl[4];
            ldmx4(bh, sB0h + np * 16 * 256 + uB);
            ldmx4(bl, sB0l + np * 16 * 256 + uB);
            #pragma unroll
            for (int mt = 0; mt < 2; mt++) {
                mma_f16(acc[mt][2 * np],     aHi[mt], bh[0], bh[1]);
                mma_f16(acc[mt][2 * np + 1], aHi[mt], bh[2], bh[3]);
                mma_f16(acc[mt][2 * np],     aLo[mt], bh[0], bh[1]);
                mma_f16(acc[mt][2 * np + 1], aLo[mt], bh[2], bh[3]);
                mma_f16(acc[mt][2 * np],     aHi[mt], bl[0], bl[1]);
                mma_f16(acc[mt][2 * np + 1], aHi[mt], bl[2], bl[3]);
            }
        }
    }

    __syncthreads();
    float* stg = (float*)sm;
    const int g = lane >> 2, tig = lane & 3;
    #pragma unroll
    for (int mt = 0; mt < 2; mt++) {
        const int r0 = wm * 32 + mt * 16 + g;
        #pragma unroll
        for (int nt = 0; nt < 4; nt++) {
            const int col = wn * 32 + nt * 8 + 2 * tig;
            *(float2*)(stg + r0 * EPAD + col)       = make_float2(acc[mt][nt][0], acc[mt][nt][1]);
            *(float2*)(stg + (r0 + 8) * EPAD + col) = make_float2(acc[mt][nt][2], acc[mt][nt][3]);
        }
    }
    __syncthreads();
    #pragma unroll 4
    for (int i = tid; i < 128 * 16; i += 256) {
        const int row = i >> 4, u = i & 15, col = u * 4;
        float4 v = *(const float4*)(stg + row * EPAD + col);
        v.x += sbias[col]; v.y += sbias[col + 1]; v.z += sbias[col + 2]; v.w += sbias[col + 3];
        *(float4*)(out + (long long)(m0 + row) * ldout + n0 + col) = v;
    }
}

// ============================================================================
// k_head: persistent-strip single-term fp16 head GEMM (unchanged from R12-14).
// ============================================================================
#define NT_STRIP 10
#define HD_SMEM (A_TILE + 2 * B_TILE + NT_STRIP * 64 * 4)

__global__ void __launch_bounds__(256, 2) k_head(
    const __half* __restrict__ Ahi_g, const __half* __restrict__ Bhi_g,
    float* __restrict__ out, const float* __restrict__ bias)
{
    extern __shared__ __align__(16) char sm[];
    char* A  = sm;
    char* Bb = sm + A_TILE;
    float* sbias = (float*)(sm + A_TILE + 2 * B_TILE);

    const int tid = threadIdx.x, w = tid >> 5, lane = tid & 31;
    const int wm = w >> 1, wn = w & 1;
    const int m0 = blockIdx.x * 128;
    const int nbase = blockIdx.y * (NT_STRIP * 64);

    {
        const __half* Ag = Ahi_g + (long long)m0 * 128;
        #pragma unroll 2
        for (int i = tid; i < 128 * 16; i += 256) {
            int row = i >> 4, u = i & 15;
            CP_ASYNC16(smem_u32(A + tswz(row, u)), Ag + (long long)row * 128 + u * 8);
        }
        const __half* Bg = Bhi_g + (long long)nbase * 128;
        for (int i = tid; i < 64 * 16; i += 256) {
            int row = i >> 4, u = i & 15;
            CP_ASYNC16(smem_u32(Bb + tswz(row, u)), Bg + (long long)row * 128 + u * 8);
        }
        CP_COMMIT();
        for (int i = tid; i < NT_STRIP * 64; i += 256) sbias[i] = bias[nbase + i];
        CP_WAIT0();
        __syncthreads();
    }

    const int sw = lane & 7;
    const int arow = wm * 32 + (lane & 15);
    const int akh  = lane >> 4;
    const int brow = wn * 32 + (lane & 7) + 8 * (lane >> 4);
    const int bkh  = (lane >> 3) & 1;
    const uint32_t sA0 = smem_u32(A) + arow * 256;
    const int g = lane >> 2, tig = lane & 3;

    int buf = 0;
    for (int ti = 0; ti < NT_STRIP; ti++) {
        if (ti < NT_STRIP - 1) {
            const __half* Bg = Bhi_g + (long long)(nbase + (ti + 1) * 64) * 128;
            char* Bn = Bb + (buf ^ 1) * B_TILE;
            for (int i = tid; i < 64 * 16; i += 256) {
                int row = i >> 4, u = i & 15;
                CP_ASYNC16(smem_u32(Bn + tswz(row, u)), Bg + (long long)row * 128 + u * 8);
            }
            CP_COMMIT();
        }

        const uint32_t sB0 = smem_u32(Bb + buf * B_TILE) + brow * 256;
        float acc[2][4][4];
        #pragma unroll
        for (int mt = 0; mt < 2; mt++)
            #pragma unroll
            for (int nt = 0; nt < 4; nt++)
                #pragma unroll
                for (int q = 0; q < 4; q++) acc[mt][nt][q] = 0.0f;

        #pragma unroll
        for (int ks = 0; ks < 8; ks++) {
            const uint32_t uA = (uint32_t)(((2 * ks + akh) ^ sw) << 4);
            const uint32_t uB = (uint32_t)(((2 * ks + bkh) ^ sw) << 4);
            uint32_t aHi[2][4];
            ldmx4(aHi[0], sA0 + uA);
            ldmx4(aHi[1], sA0 + 16 * 256 + uA);
            #pragma unroll
            for (int np = 0; np < 2; np++) {
                uint32_t bh[4];
                ldmx4(bh, sB0 + np * 16 * 256 + uB);
                #pragma unroll
                for (int mt = 0; mt < 2; mt++) {
                    mma_f16(acc[mt][2 * np],     aHi[mt], bh[0], bh[1]);
                    mma_f16(acc[mt][2 * np + 1], aHi[mt], bh[2], bh[3]);
                }
            }
        }

        const int n0 = nbase + ti * 64;
        #pragma unroll
        for (int mt = 0; mt < 2; mt++) {
            const long long r0 = (long long)(m0 + wm * 32 + mt * 16 + g) * VOCAB + n0;
            const long long r1 = r0 + 8LL * VOCAB;
            #pragma unroll
            for (int nt = 0; nt < 4; nt++) {
                const int col = wn * 32 + nt * 8 + 2 * tig;
                const float bx = sbias[ti * 64 + col], by = sbias[ti * 64 + col + 1];
                *(float2*)(out + r0 + col) = make_float2(acc[mt][nt][0] + bx, acc[mt][nt][1] + by);
                *(float2*)(out + r1 + col) = make_float2(acc[mt][nt][2] + bx, acc[mt][nt][3] + by);
            }
        }

        if (ti < NT_STRIP - 1) {
            CP_WAIT0();
            __syncthreads();
            buf ^= 1;
        }
    }
}

// ============================================================================
// Kernel B: cluster-of-2 MMA RNN scan, 2-term (R14 structure — monolithic MMA
// loop). Single change vs R14: the remote-arrival mbar_wait is issued BEFORE
// __syncthreads at the step bottom, so DSMEM flight + bar overlap (max not
// sum). Acquire-wait still precedes all reads of remote data; the bar still
// precedes all reads of local stores.
// ============================================================================
#define SXP 260
#define S2_OFF_W    0                         // local 64 W rows: hi 16KB + lo 16KB
#define S2_OFF_AT   32768                     // A tiles: buf*4096, hi only (8KB)
#define S2_OFF_SX   40960                     // 16 x SXP ints (16640 B)
#define S2_OFF_MBAR (S2_OFF_SX + 16 * SXP * 4)
#define S2_SMEM     (S2_OFF_MBAR + 64)

__global__ void __launch_bounds__(256, 1) __cluster_dims__(2, 1, 1)
k_rnn_cluster(const int* __restrict__ x)
{
    extern __shared__ __align__(16) char sm[];
    char* WHhi = sm + S2_OFF_W;
    char* WHlo = sm + S2_OFF_W + 16384;
    char* AT   = sm + S2_OFF_AT;
    int*  sx   = (int*)(sm + S2_OFF_SX);

    const int tid = threadIdx.x, w = tid >> 5, lane = tid & 31;
    const uint32_t rank = my_cluster_rank();
    const uint32_t peer = rank ^ 1;
    const int b0 = (blockIdx.x >> 1) * 16;
    const uint32_t mbar0 = smem_u32(sm) + S2_OFF_MBAR;
    const uint32_t mbar1 = mbar0 + 8;

    // prologue: local W half, x stage, zero h buffer 0 (both bufs), mbar init
    load_tile(g_WHhi + (long long)rank * 64 * 128, WHhi, 64, tid);
    load_tile(g_WHlo + (long long)rank * 64 * 128, WHlo, 64, tid);
    for (int i = tid; i < 16 * SEQ; i += 256) {
        int row = i >> 8, t = i & 255;
        sx[row * SXP + t] = x[(b0 + row) * SEQ + t];
    }
    for (int i = tid; i < 512; i += 256)
        ((uint4*)AT)[i] = make_uint4(0, 0, 0, 0);
    if (tid == 0) { MBAR_INIT(mbar0, 1); MBAR_INIT(mbar1, 1); }
    __syncthreads();

    // preload B fragments (W_hh local rows w*8..w*8+8, full K) — static
    const int l15 = lane & 15;
    const int browB = w * 8 + (l15 & 7);
    const int bkhB  = (l15 >> 3) & 1;
    const int swB   = l15 & 7;
    const uint32_t sBh = smem_u32(WHhi) + browB * 256;
    const uint32_t sBl = smem_u32(WHlo) + browB * 256;
    uint32_t bfh[8][2], bfl[8][2];
    #pragma unroll
    for (int ks = 0; ks < 8; ks++) {
        const uint32_t uB = (uint32_t)(((2 * ks + bkhB) ^ swB) << 4);
        ldmx2(bfh[ks], sBh + uB);
        ldmx2(bfl[ks], sBl + uB);
    }

    // A-frag addressing
    const int arow = lane & 15;
    const int akh  = lane >> 4;
    const int swA  = lane & 7;
    const uint32_t sAT = smem_u32(AT);
    const uint32_t aH0 = sAT + arow * 256;

    // epilogue addressing: thread owns rows g, g+8; cols jc = rank*64+w*8+2*tig
    const int g = lane >> 2, tig = lane & 3;
    const int jc = (int)rank * 64 + w * 8 + 2 * tig;
    const int ustore = (int)rank * 8 + w;
    const uint32_t st0 = (uint32_t)(g * 256 + ((ustore ^ (g & 7)) << 4) + 4 * tig);
    const uint32_t st1 = (uint32_t)((g + 8) * 256 + ((ustore ^ ((g + 8) & 7)) << 4) + 4 * tig);

    // mbar init on both CTAs must complete before any remote traffic
    CLUSTER_SYNC();
    const uint32_t peerAT    = mapa_peer(sAT, peer);
    const uint32_t peerMbar0 = mapa_peer(mbar0, peer);
    const uint32_t peerMbar1 = mapa_peer(mbar1, peer);

    int cur = 0;
    for (int t = 0; t < SEQ; t++) {
        const uint32_t myMbar = (t & 1) ? mbar1 : mbar0;
        const uint32_t pMbar  = (t & 1) ? peerMbar1 : peerMbar0;
        if (tid == 0) MBAR_EXPECT_TX(myMbar, 2048);

        // P gather (consumed at epilogue; L2 latency hides under MMA)
        const int idx0 = sx[g * SXP + t];
        const int idx1 = sx[(g + 8) * SXP + t];
        const float2 p0 = *(const float2*)(g_P + idx0 * HID + jc);
        const float2 p1 = *(const float2*)(g_P + idx1 * HID + jc);

        float aH[4] = {0, 0, 0, 0}, aM[4] = {0, 0, 0, 0};
        const uint32_t aAddrH = aH0 + cur * 4096;
        #pragma unroll
        for (int ks = 0; ks < 8; ks++) {
            const uint32_t uA = (uint32_t)(((2 * ks + akh) ^ swA) << 4);
            uint32_t ahi[4];
            ldmx4(ahi, aAddrH + uA);
            mma_f16(aH, ahi, bfh[ks][0], bfh[ks][1]);
            mma_f16(aM, ahi, bfl[ks][0], bfl[ks][1]);
        }

        // epilogue: v = mma + P; h = tanh(v); pack fp16; store local + peer
        const int nxt = cur ^ 1;
        char* DhiL = AT + nxt * 4096;
        const uint32_t DhiR = peerAT + nxt * 4096;
        const float h00 = fast_tanh(aH[0] + aM[0] + p0.x);
        const float h01 = fast_tanh(aH[1] + aM[1] + p0.y);
        const float h10 = fast_tanh(aH[2] + aM[2] + p1.x);
        const float h11 = fast_tanh(aH[3] + aM[3] + p1.y);
        const uint32_t hi0 = pack_h2(h00, h01);
        const uint32_t hi1 = pack_h2(h10, h11);
        *(uint32_t*)(DhiL + st0) = hi0;
        *(uint32_t*)(DhiL + st1) = hi1;
        ST_ASYNC_U32(DhiR + st0, hi0, pMbar);
        ST_ASYNC_U32(DhiR + st1, hi1, pMbar);

        // wait FIRST (remote flight overlaps other warps' arrival skew), then
        // the CTA barrier (orders local stores). Same guarantees as R14, but
        // cost is max(wait, bar-skew) not sum.
        mbar_wait_acq(myMbar, (uint32_t)((t >> 1) & 1));
        __syncthreads();
        cur = nxt;
    }

    // write final h — rank 0 only
    if (rank == 0) {
        char* Fhi = AT + cur * 4096;
        for (int i = tid; i < 16 * 64; i += 256) {
            const int row = i >> 6, cp = i & 63;
            const uint32_t off = (uint32_t)(row * 256 + (((cp >> 2) ^ (row & 7)) << 4) + (cp & 3) * 4);
            ((uint32_t*)g_Hhi)[(b0 + row) * 64 + cp] = *(const uint32_t*)(Fhi + off);
        }
    }
    CLUSTER_SYNC();   // no CTA exits while peer traffic may be in flight
}

// ============================================================================
// launch — fork-join dual stream: W_hh/W_fc cvts overlap emb/W_ih cvts + gemmA
// ============================================================================
extern "C" void kernel_launch(void* const* d_in, const int* in_sizes, int n_in,
                              void* d_out, int out_size) {
    const int*   x    = (const int*)d_in[0];     // int32: JAX downcasts int64
    const float* emb  = (const float*)d_in[1];
    const float* W_ih = (const float*)d_in[2];
    const float* W_hh = (const float*)d_in[3];
    const float* b_ih = (const float*)d_in[4];
    const float* b_hh = (const float*)d_in[5];
    const float* W_fc = (const float*)d_in[6];
    const float* b_fc = (const float*)d_in[7];
    float*       out  = (float*)d_out;

    static float* P_p = nullptr;
    static __half *Ehi_p, *Elo_p, *Whi_p, *IHhi_p, *IHlo_p;
    static __half *WHhi_p, *WHlo_p, *Hhi_p;
    static cudaStream_t s2 = nullptr;
    static cudaEvent_t evFork = nullptr, evJoin = nullptr;
    if (!P_p) {
        cudaGetSymbolAddress((void**)&P_p,    g_P);
        cudaGetSymbolAddress((void**)&Ehi_p,  g_Ehi);
        cudaGetSymbolAddress((void**)&Elo_p,  g_Elo);
        cudaGetSymbolAddress((void**)&Whi_p,  g_Whi);
        cudaGetSymbolAddress((void**)&IHhi_p, g_IHhi);
        cudaGetSymbolAddress((void**)&IHlo_p, g_IHlo);
        cudaGetSymbolAddress((void**)&WHhi_p, g_WHhi);
        cudaGetSymbolAddress((void**)&WHlo_p, g_WHlo);
        cudaGetSymbolAddress((void**)&Hhi_p,  g_Hhi);
        cudaFuncSetAttribute(k_gemm,        cudaFuncAttributeMaxDynamicSharedMemorySize, GEMM_SMEM);
        cudaFuncSetAttribute(k_head,        cudaFuncAttributeMaxDynamicSharedMemorySize, HD_SMEM);
        cudaFuncSetAttribute(k_rnn_cluster, cudaFuncAttributeMaxDynamicSharedMemorySize, S2_SMEM);
        cudaStreamCreateWithFlags(&s2, cudaStreamNonBlocking);
        cudaEventCreateWithFlags(&evFork, cudaEventDisableTiming);
        cudaEventCreateWithFlags(&evJoin, cudaEventDisableTiming);
    }

    // fork: W_hh + W_fc conversions run on s2, overlapping gemmA's chain
    cudaEventRecord(evFork, 0);
    cudaStreamWaitEvent(s2, evFork, 0);
    k_cvt<<<HID / 8, 256, 0, s2>>>(W_hh, HID, WHhi_p, WHlo_p);
    k_cvt_hi<<<VOCAB / 8, 256, 0, s2>>>(W_fc, HID, Whi_p);
    cudaEventRecord(evJoin, s2);

    // main chain: emb/W_ih cvts -> gemmA
    k_cvt<<<VOCAB / 8, 256>>>(emb,  EMBED, Ehi_p,  Elo_p);
    k_cvt<<<HID / 8,   256>>>(W_ih, EMBED, IHhi_p, IHlo_p);
    k_gemm<<<dim3(VOCAB / 128, HID / 64), 256, GEMM_SMEM>>>(
        Ehi_p, Elo_p, IHhi_p, IHlo_p, P_p, HID, b_ih, b_hh);

    // join before scan (needs g_P + W_hh splits)
    cudaStreamWaitEvent(0, evJoin, 0);

    // recurrent scan: cluster-of-2, 2-term, st.async tx sync
    k_rnn_cluster<<<BATCH / 8, 256, S2_SMEM>>>(x);

    // head: persistent-strip single-term fp16
    k_head<<<dim3(BATCH / 128, VOCAB / (NT_STRIP * 64)), 256, HD_SMEM>>>(
        Hhi_p, Whi_p, out, b_fc);
}